// round 13
// baseline (speedup 1.0000x reference)
#include <cuda_runtime.h>
#include <cuda_fp16.h>
#include <cstdint>

#define BATCH 2
#define SEQ 2048
#define DMODEL 768
#define NHEAD 12
#define HDIM 64
#define MROWS (BATCH * SEQ)          // 4096
#define BHEADS (BATCH * NHEAD)       // 24

// ---------------- scratch (all fp16) ----------------
__device__ __half g_q[BHEADS * SEQ * HDIM];   // pre-scaled, [bh][s][d]
__device__ __half g_k[BHEADS * SEQ * HDIM];   // [bh][s][d]
__device__ __half g_v[BHEADS * SEQ * HDIM];   // TRANSPOSED [bh][d][s]
__device__ __half g_ctx[MROWS * DMODEL];      // [m][768]
__device__ __half g_aq[MROWS * DMODEL];       // fp16 copies of inputs
__device__ __half g_ak[MROWS * DMODEL];
__device__ __half g_av[MROWS * DMODEL];
__device__ __half g_wq[DMODEL * DMODEL];      // fp16 copies of weights
__device__ __half g_wk[DMODEL * DMODEL];
__device__ __half g_wv[DMODEL * DMODEL];
__device__ __half g_wo[DMODEL * DMODEL];

__device__ __forceinline__ uint32_t pack2(float a, float b) {
    __half2 h = __floats2half2_rn(a, b);
    return *reinterpret_cast<uint32_t*>(&h);
}

// m16n8k16 fp16 mma, fp32 accumulate
__device__ __forceinline__ void mma_f16(float c[4], const uint32_t a[4], const uint32_t b[2]) {
    asm volatile(
        "mma.sync.aligned.m16n8k16.row.col.f32.f16.f16.f32 "
        "{%0,%1,%2,%3}, {%4,%5,%6,%7}, {%8,%9}, {%0,%1,%2,%3};"
        : "+f"(c[0]), "+f"(c[1]), "+f"(c[2]), "+f"(c[3])
        : "r"(a[0]), "r"(a[1]), "r"(a[2]), "r"(a[3]), "r"(b[0]), "r"(b[1]));
}

__device__ __forceinline__ void ldsm_x4(uint32_t r[4], uint32_t saddr) {
    asm volatile("ldmatrix.sync.aligned.m8n8.x4.shared.b16 {%0,%1,%2,%3}, [%4];"
        : "=r"(r[0]), "=r"(r[1]), "=r"(r[2]), "=r"(r[3]) : "r"(saddr));
}

__device__ __forceinline__ void cp16(uint32_t s, const void* g) {
    asm volatile("cp.async.cg.shared.global [%0], [%1], 16;" :: "r"(s), "l"(g));
}
__device__ __forceinline__ void cp_commit() { asm volatile("cp.async.commit_group;"); }
__device__ __forceinline__ void cp_wait0()  { asm volatile("cp.async.wait_group 0;"); }
template<int N>
__device__ __forceinline__ void cp_waitN()  { asm volatile("cp.async.wait_group %0;" :: "n"(N)); }

// =================================================================
// fp32 -> fp16 bulk converter. grid (blocks, 7); 8 floats/thread/iter
// =================================================================
struct CvtArgs {
    const float4* src[7];
    uint4*        dst[7];
    int           n8[7];
};

__global__ __launch_bounds__(256)
void cvt_f16_kernel(CvtArgs a)
{
    const int z = blockIdx.y;
    const float4* __restrict__ s = a.src[z];
    uint4* __restrict__ d = a.dst[z];
    const int n8 = a.n8[z];
    for (int i = blockIdx.x * blockDim.x + threadIdx.x; i < n8;
         i += gridDim.x * blockDim.x) {
        float4 lo = s[2 * i], hi = s[2 * i + 1];
        uint4 u;
        u.x = pack2(lo.x, lo.y); u.y = pack2(lo.z, lo.w);
        u.z = pack2(hi.x, hi.y); u.w = pack2(hi.z, hi.w);
        d[i] = u;
    }
}

// =================================================================
// Fused fp16 GEMM: out[m][n] = A[m][:] . W[n][:] + bias[n]
// CTA 64x128, BK=32 halfs, 256 threads (8 warps), warp tile 32x32.
// 4-stage cp.async pipeline, ldmatrix fragments, m16n8k16 mma.
// split: 0 plain f32 out, 1 head-split fp16, 2 head-split transposed fp16.
// =================================================================
struct GemmArgs {
    const __half* A[3];
    const __half* W[3];
    const float*  bias[3];
    void*         out[3];
    float         scale[3];
    int           split[3];
};

#define RPITCH 80    // bytes per smem row: 64B data + 16B pad (conflict-free)
#define GBM 64
#define GBN 128
#define GNT 256
#define GNS 4
#define GSTAGE_B ((GBM + GBN) * RPITCH)        // 15360 B
#define GEMM_SMEM (GNS * GSTAGE_B)             // 61440 B

__global__ __launch_bounds__(GNT, 3)
void gemm_f16(GemmArgs args)
{
    extern __shared__ uint32_t gsm[];
    const uint32_t sb = (uint32_t)__cvta_generic_to_shared(gsm);

    const int z = blockIdx.z;
    const __half* __restrict__ A = args.A[z];
    const __half* __restrict__ W = args.W[z];
    const float* __restrict__ bias = args.bias[z];
    const float scale = args.scale[z];
    const int   split = args.split[z];

    const int tid = threadIdx.x;
    const int w = tid >> 5, lane = tid & 31;
    const int gid = lane >> 2, l4 = lane & 3;
    const int bm = blockIdx.x * GBM;
    const int bn = blockIdx.y * GBN;
    const int wm = (w & 1) * 32;        // 2 warps in M (32 rows each)
    const int wn = (w >> 1) * 32;       // 4 warps in N (32 cols each)

    const int rowl = lane & 15;                 // ldmatrix row-within-16
    const int hi16 = (lane >> 4) * 16;          // ldmatrix 16B half select

    auto stage = [&](int it, int s) {
        const uint32_t ab = sb + s * GSTAGE_B;
        const uint32_t bb = ab + GBM * RPITCH;
#pragma unroll
        for (int i = 0; i < 3; i++) {           // (64+128)*4 / 256 = 3
            const int idx = i * GNT + tid;
            const int r = idx >> 2;
            const int c = idx & 3;
            if (r < GBM)
                cp16(ab + (uint32_t)(r * RPITCH + c * 16),
                     A + (size_t)(bm + r) * DMODEL + it * 32 + c * 8);
            else
                cp16(bb + (uint32_t)((r - GBM) * RPITCH + c * 16),
                     W + (size_t)(bn + r - GBM) * DMODEL + it * 32 + c * 8);
        }
        cp_commit();
    };

    float acc[2][4][4];
#pragma unroll
    for (int i = 0; i < 2; i++)
#pragma unroll
        for (int j = 0; j < 4; j++)
#pragma unroll
            for (int t = 0; t < 4; t++) acc[i][j][t] = 0.f;

    const int nIter = DMODEL / 32;   // 24
#pragma unroll
    for (int p = 0; p < GNS - 1; p++) stage(p, p);

    for (int it = 0; it < nIter; it++) {
        const int s = it & (GNS - 1);
        cp_waitN<GNS - 2>();
        __syncthreads();

        const uint32_t aB = sb + s * GSTAGE_B;
        const uint32_t bB = aB + GBM * RPITCH;

#pragma unroll
        for (int kb = 0; kb < 64; kb += 32) {     // two k16 blocks (bytes)
            uint32_t af[2][4], bf[4][2];
#pragma unroll
            for (int mt = 0; mt < 2; mt++)
                ldsm_x4(af[mt], aB + (uint32_t)((wm + mt * 16 + rowl) * RPITCH + kb + hi16));
#pragma unroll
            for (int ntp = 0; ntp < 2; ntp++) {
                uint32_t r[4];
                ldsm_x4(r, bB + (uint32_t)((wn + ntp * 16 + rowl) * RPITCH + kb + hi16));
                bf[2 * ntp][0] = r[0]; bf[2 * ntp][1] = r[2];
                bf[2 * ntp + 1][0] = r[1]; bf[2 * ntp + 1][1] = r[3];
            }
#pragma unroll
            for (int mt = 0; mt < 2; mt++)
#pragma unroll
                for (int nt = 0; nt < 4; nt++)
                    mma_f16(acc[mt][nt], af[mt], bf[nt]);
        }

        if (it + GNS - 1 < nIter) stage(it + GNS - 1, (it + GNS - 1) & (GNS - 1));
        else                      cp_commit();
    }

    // epilogue
#pragma unroll
    for (int mt = 0; mt < 2; mt++) {
#pragma unroll
        for (int nt = 0; nt < 4; nt++) {
#pragma unroll
            for (int half = 0; half < 2; half++) {
                const int m = bm + wm + mt * 16 + gid + half * 8;
                const int n = bn + wn + nt * 8 + 2 * l4;     // even
                const float v0 = (acc[mt][nt][half * 2 + 0] + bias[n]) * scale;
                const float v1 = (acc[mt][nt][half * 2 + 1] + bias[n + 1]) * scale;
                if (split == 0) {
                    float* of = (float*)args.out[z];
                    of[(size_t)m * DMODEL + n] = v0;
                    of[(size_t)m * DMODEL + n + 1] = v1;
                } else {
                    const int b = m >> 11;
                    const int sdx = m & (SEQ - 1);
                    const int h = n >> 6;
                    const int d = n & (HDIM - 1);
                    __half* o16 = (__half*)args.out[z];
                    if (split == 1) {
                        *(uint32_t*)&o16[(((size_t)(b * NHEAD + h) * SEQ) + sdx) * HDIM + d] =
                            pack2(v0, v1);
                    } else {   // transposed [bh][d][s]
                        o16[(((size_t)(b * NHEAD + h) * HDIM) + d)     * SEQ + sdx] = __float2half_rn(v0);
                        o16[(((size_t)(b * NHEAD + h) * HDIM) + d + 1) * SEQ + sdx] = __float2half_rn(v1);
                    }
                }
            }
        }
    }
}

// =================================================================
// Flash attention (causal), fp16 mma, shuffle-free PV.  (round-10 proven)
// 128 threads (4 warps), q-tile 64. K [bh][s][d], V TRANSPOSED [bh][d][s].
// Double-buffered cp.async; longest-qt-first scheduling.
// =================================================================
#define KPB 144                               // bytes per smem row (128 data + 16 pad)
#define TB  (64 * KPB)                        // 9216 bytes per tile buffer
#define ATTN_SMEM (4 * TB)                    // 36864 B

__global__ __launch_bounds__(128, 3)
void attn_f16(const __half* __restrict__ Q, const __half* __restrict__ K,
              const __half* __restrict__ V, __half* __restrict__ ctx)
{
    extern __shared__ uint32_t smu[];
    const uint32_t smem_u32 = (uint32_t)__cvta_generic_to_shared(smu);

    const int tid = threadIdx.x;
    const int w = tid >> 5, lane = tid & 31;
    const int gid = lane >> 2, l4 = lane & 3;
    const int bh = blockIdx.x;
    const int qt = (SEQ / 64 - 1) - blockIdx.y;   // reversed: longest first
    const int m0 = w * 16;

    const int rowl = lane & 15;
    const int hi16 = (lane >> 4) * 16;

    const __half* Kg = K + ((size_t)bh * SEQ) * HDIM;   // [s][d]
    const __half* Vg = V + ((size_t)bh * HDIM) * SEQ;   // [d][s]

    auto stage = [&](int jt, int buf) {
        const uint32_t ksb = smem_u32 + (uint32_t)(buf * TB);
        const uint32_t vsb = smem_u32 + (uint32_t)((2 + buf) * TB);
#pragma unroll
        for (int i = 0; i < 8; i++) {
            const int idx = i * 128 + tid;     // 0..1023 cp16 ops
            if (idx < 512) {
                const int r = idx >> 3, c = idx & 7;
                cp16(ksb + (uint32_t)(r * KPB + c * 16),
                     Kg + (size_t)(jt * 64 + r) * HDIM + c * 8);
            } else {
                const int r = (idx - 512) >> 3, c = idx & 7;
                cp16(vsb + (uint32_t)(r * KPB + c * 16),
                     Vg + (size_t)r * SEQ + jt * 64 + c * 8);
            }
        }
        cp_commit();
    };

    // Q fragments directly from gmem (k16 blocks, kt 0..3)
    uint32_t qf[4][4];
    {
        const __half* Qg = Q + ((size_t)bh * SEQ + qt * 64) * HDIM;
#pragma unroll
        for (int kt = 0; kt < 4; kt++) {
            const __half* base = Qg + (m0 + gid) * HDIM + kt * 16 + 2 * l4;
            qf[kt][0] = *(const uint32_t*)(base);
            qf[kt][1] = *(const uint32_t*)(base + 8 * HDIM);
            qf[kt][2] = *(const uint32_t*)(base + 8);
            qf[kt][3] = *(const uint32_t*)(base + 8 * HDIM + 8);
        }
    }

    stage(0, 0);
    cp_wait0();
    __syncthreads();

    float o[8][4];
#pragma unroll
    for (int dt = 0; dt < 8; dt++)
#pragma unroll
        for (int t = 0; t < 4; t++) o[dt][t] = 0.f;

    float m_a = -1e30f, m_b = -1e30f;
    float l_a = 0.f, l_b = 0.f;

    const int ntiles = qt + 1;
    for (int jt = 0; jt < ntiles; jt++) {
        const int buf = jt & 1;
        if (jt + 1 < ntiles) stage(jt + 1, buf ^ 1);

        const uint32_t ksB = smem_u32 + (uint32_t)(buf * TB);
        const uint32_t vtB = smem_u32 + (uint32_t)((2 + buf) * TB);

        // ---- S = Q K^T ----
        float s[8][4];
#pragma unroll
        for (int nt = 0; nt < 8; nt++)
#pragma unroll
            for (int t = 0; t < 4; t++) s[nt][t] = 0.f;

#pragma unroll
        for (int kt = 0; kt < 4; kt++) {
            uint32_t bf[8][2];
#pragma unroll
            for (int ntp = 0; ntp < 4; ntp++) {
                uint32_t r[4];
                ldsm_x4(r, ksB + (uint32_t)((ntp * 16 + rowl) * KPB + kt * 32 + hi16));
                bf[2 * ntp][0] = r[0]; bf[2 * ntp][1] = r[2];
                bf[2 * ntp + 1][0] = r[1]; bf[2 * ntp + 1][1] = r[3];
            }
#pragma unroll
            for (int nt = 0; nt < 8; nt++)
                mma_f16(s[nt], qf[kt], bf[nt]);
        }

        // ---- causal mask on diagonal tile ----
        if (jt == qt) {
            const int ra = m0 + gid, rb = ra + 8;
#pragma unroll
            for (int nt = 0; nt < 8; nt++) {
                const int c = nt * 8 + 2 * l4;
                if (c > ra)     s[nt][0] = -1e30f;
                if (c + 1 > ra) s[nt][1] = -1e30f;
                if (c > rb)     s[nt][2] = -1e30f;
                if (c + 1 > rb) s[nt][3] = -1e30f;
            }
        }

        // ---- online softmax ----
        float mxa = -1e30f, mxb = -1e30f;
#pragma unroll
        for (int nt = 0; nt < 8; nt++) {
            mxa = fmaxf(mxa, fmaxf(s[nt][0], s[nt][1]));
            mxb = fmaxf(mxb, fmaxf(s[nt][2], s[nt][3]));
        }
        mxa = fmaxf(mxa, __shfl_xor_sync(0xffffffffu, mxa, 1));
        mxa = fmaxf(mxa, __shfl_xor_sync(0xffffffffu, mxa, 2));
        mxb = fmaxf(mxb, __shfl_xor_sync(0xffffffffu, mxb, 1));
        mxb = fmaxf(mxb, __shfl_xor_sync(0xffffffffu, mxb, 2));

        const float mna = fmaxf(m_a, mxa);
        const float mnb = fmaxf(m_b, mxb);
        const float alpha_a = __expf(m_a - mna);
        const float alpha_b = __expf(m_b - mnb);
        m_a = mna; m_b = mnb;

        float suma = 0.f, sumb = 0.f;
#pragma unroll
        for (int nt = 0; nt < 8; nt++) {
            s[nt][0] = __expf(s[nt][0] - mna);
            s[nt][1] = __expf(s[nt][1] - mna);
            s[nt][2] = __expf(s[nt][2] - mnb);
            s[nt][3] = __expf(s[nt][3] - mnb);
            suma += s[nt][0] + s[nt][1];
            sumb += s[nt][2] + s[nt][3];
        }
        l_a = l_a * alpha_a + suma;
        l_b = l_b * alpha_b + sumb;

#pragma unroll
        for (int dt = 0; dt < 8; dt++) {
            o[dt][0] *= alpha_a; o[dt][1] *= alpha_a;
            o[dt][2] *= alpha_b; o[dt][3] *= alpha_b;
        }

        // ---- O += P V : fp16 P fragment == C fragment layout (no shuffles) ----
#pragma unroll
        for (int kt = 0; kt < 4; kt++) {
            uint32_t pf[4];
            pf[0] = pack2(s[2 * kt][0],     s[2 * kt][1]);
            pf[1] = pack2(s[2 * kt][2],     s[2 * kt][3]);
            pf[2] = pack2(s[2 * kt + 1][0], s[2 * kt + 1][1]);
            pf[3] = pack2(s[2 * kt + 1][2], s[2 * kt + 1][3]);

            uint32_t bv[8][2];
#pragma unroll
            for (int dtp = 0; dtp < 4; dtp++) {
                uint32_t r[4];
                ldsm_x4(r, vtB + (uint32_t)((dtp * 16 + rowl) * KPB + kt * 32 + hi16));
                bv[2 * dtp][0] = r[0]; bv[2 * dtp][1] = r[2];
                bv[2 * dtp + 1][0] = r[1]; bv[2 * dtp + 1][1] = r[3];
            }
#pragma unroll
            for (int dt = 0; dt < 8; dt++)
                mma_f16(o[dt], pf, bv[dt]);
        }

        cp_wait0();
        __syncthreads();
    }

    // ---- finalize ----
    l_a += __shfl_xor_sync(0xffffffffu, l_a, 1);
    l_a += __shfl_xor_sync(0xffffffffu, l_a, 2);
    l_b += __shfl_xor_sync(0xffffffffu, l_b, 1);
    l_b += __shfl_xor_sync(0xffffffffu, l_b, 2);
    const float ia = 1.f / l_a, ib = 1.f / l_b;

    const int b = bh / NHEAD;
    const int h = bh % NHEAD;
    const int sa = qt * 64 + m0 + gid;
    const int sb2 = sa + 8;
    __half* da = ctx + ((size_t)(b * SEQ + sa)) * DMODEL + h * HDIM;
    __half* db = ctx + ((size_t)(b * SEQ + sb2)) * DMODEL + h * HDIM;
#pragma unroll
    for (int dt = 0; dt < 8; dt++) {
        const int c = dt * 8 + 2 * l4;       // even
        *(uint32_t*)&da[c] = pack2(o[dt][0] * ia, o[dt][1] * ia);
        *(uint32_t*)&db[c] = pack2(o[dt][2] * ib, o[dt][3] * ib);
    }
}

// =================================================================
extern "C" void kernel_launch(void* const* d_in, const int* in_sizes, int n_in,
                              void* d_out, int out_size)
{
    (void)in_sizes; (void)n_in; (void)out_size;
    const float* query = (const float*)d_in[0];
    const float* key   = (const float*)d_in[1];
    const float* value = (const float*)d_in[2];
    const float* Wq = (const float*)d_in[4];
    const float* bq = (const float*)d_in[5];
    const float* Wk = (const float*)d_in[6];
    const float* bk = (const float*)d_in[7];
    const float* Wv = (const float*)d_in[8];
    const float* bv = (const float*)d_in[9];
    const float* Wo = (const float*)d_in[10];
    const float* bo = (const float*)d_in[11];
    float* out = (float*)d_out;

    __half *qp, *kp, *vp, *cp;
    __half *aq, *ak, *av, *wq, *wk, *wv, *wo;
    cudaGetSymbolAddress((void**)&qp, g_q);
    cudaGetSymbolAddress((void**)&kp, g_k);
    cudaGetSymbolAddress((void**)&vp, g_v);
    cudaGetSymbolAddress((void**)&cp, g_ctx);
    cudaGetSymbolAddress((void**)&aq, g_aq);
    cudaGetSymbolAddress((void**)&ak, g_ak);
    cudaGetSymbolAddress((void**)&av, g_av);
    cudaGetSymbolAddress((void**)&wq, g_wq);
    cudaGetSymbolAddress((void**)&wk, g_wk);
    cudaGetSymbolAddress((void**)&wv, g_wv);
    cudaGetSymbolAddress((void**)&wo, g_wo);

    static bool init = false;
    if (!init) {
        cudaFuncSetAttribute(attn_f16, cudaFuncAttributeMaxDynamicSharedMemorySize, ATTN_SMEM);
        cudaFuncSetAttribute(gemm_f16, cudaFuncAttributeMaxDynamicSharedMemorySize, GEMM_SMEM);
        init = true;
    }

    // ---- pre-convert all operands to fp16 ----
    CvtArgs cv;
    cv.src[0] = (const float4*)query; cv.dst[0] = (uint4*)aq; cv.n8[0] = MROWS * DMODEL / 8;
    cv.src[1] = (const float4*)key;   cv.dst[1] = (uint4*)ak; cv.n8[1] = MROWS * DMODEL / 8;
    cv.src[2] = (const float4*)value; cv.dst[2] = (uint4*)av; cv.n8[2] = MROWS * DMODEL / 8;
    cv.src[3] = (const float4*)Wq;    cv.dst[3] = (uint4*)wq; cv.n8[3] = DMODEL * DMODEL / 8;
    cv.src[4] = (const float4*)Wk;    cv.dst[4] = (uint4*)wk; cv.n8[4] = DMODEL * DMODEL / 8;
    cv.src[5] = (const float4*)Wv;    cv.dst[5] = (uint4*)wv; cv.n8[5] = DMODEL * DMODEL / 8;
    cv.src[6] = (const float4*)Wo;    cv.dst[6] = (uint4*)wo; cv.n8[6] = DMODEL * DMODEL / 8;
    cvt_f16_kernel<<<dim3(256, 7), 256>>>(cv);

    // ---- fused QKV projections ----
    GemmArgs qkv;
    qkv.A[0] = aq; qkv.A[1] = ak; qkv.A[2] = av;
    qkv.W[0] = wq; qkv.W[1] = wk; qkv.W[2] = wv;
    qkv.bias[0] = bq; qkv.bias[1] = bk; qkv.bias[2] = bv;
    qkv.out[0] = qp;  qkv.out[1] = kp;  qkv.out[2] = vp;
    qkv.scale[0] = 0.125f; qkv.scale[1] = 1.f; qkv.scale[2] = 1.f;
    qkv.split[0] = 1; qkv.split[1] = 1; qkv.split[2] = 2;
    dim3 gqkv(MROWS / GBM, DMODEL / GBN, 3);      // (64, 6, 3)
    gemm_f16<<<gqkv, GNT, GEMM_SMEM>>>(qkv);

    // ---- attention (round-10 proven config) ----
    dim3 gattn(BHEADS, SEQ / 64);                 // (24, 32)
    attn_f16<<<gattn, 128, ATTN_SMEM>>>(qp, kp, vp, cp);

    // ---- output projection ----
    GemmArgs og;
    og.A[0] = cp; og.W[0] = wo; og.bias[0] = bo; og.out[0] = out;
    og.scale[0] = 1.f; og.split[0] = 0;
    og.A[1] = og.A[2] = cp; og.W[1] = og.W[2] = wo;
    og.bias[1] = og.bias[2] = bo; og.out[1] = og.out[2] = out;
    og.scale[1] = og.scale[2] = 1.f; og.split[1] = og.split[2] = 0;
    dim3 gout(MROWS / GBM, DMODEL / GBN, 1);      // (64, 6)
    gemm_f16<<<gout, GNT, GEMM_SMEM>>>(og);
}

// round 14
// speedup vs baseline: 1.0162x; 1.0162x over previous
#include <cuda_runtime.h>
#include <cuda_fp16.h>
#include <cstdint>

#define BATCH 2
#define SEQ 2048
#define DMODEL 768
#define NHEAD 12
#define HDIM 64
#define MROWS (BATCH * SEQ)          // 4096
#define BHEADS (BATCH * NHEAD)       // 24

// ---------------- scratch (all fp16) ----------------
__device__ __half g_q[BHEADS * SEQ * HDIM];   // pre-scaled by 0.125*log2(e), [bh][s][d]
__device__ __half g_k[BHEADS * SEQ * HDIM];   // [bh][s][d]
__device__ __half g_v[BHEADS * SEQ * HDIM];   // TRANSPOSED [bh][d][s]
__device__ __half g_ctx[MROWS * DMODEL];      // [m][768]
__device__ __half g_aq[MROWS * DMODEL];       // fp16 copies of inputs
__device__ __half g_ak[MROWS * DMODEL];
__device__ __half g_av[MROWS * DMODEL];
__device__ __half g_wq[DMODEL * DMODEL];      // fp16 copies of weights
__device__ __half g_wk[DMODEL * DMODEL];
__device__ __half g_wv[DMODEL * DMODEL];
__device__ __half g_wo[DMODEL * DMODEL];

__device__ __forceinline__ uint32_t pack2(float a, float b) {
    __half2 h = __floats2half2_rn(a, b);
    return *reinterpret_cast<uint32_t*>(&h);
}

__device__ __forceinline__ float ex2(float x) {
    float r; asm("ex2.approx.f32 %0, %1;" : "=f"(r) : "f"(x)); return r;
}

// m16n8k16 fp16 mma, fp32 accumulate
__device__ __forceinline__ void mma_f16(float c[4], const uint32_t a[4], const uint32_t b[2]) {
    asm volatile(
        "mma.sync.aligned.m16n8k16.row.col.f32.f16.f16.f32 "
        "{%0,%1,%2,%3}, {%4,%5,%6,%7}, {%8,%9}, {%0,%1,%2,%3};"
        : "+f"(c[0]), "+f"(c[1]), "+f"(c[2]), "+f"(c[3])
        : "r"(a[0]), "r"(a[1]), "r"(a[2]), "r"(a[3]), "r"(b[0]), "r"(b[1]));
}

__device__ __forceinline__ void ldsm_x4(uint32_t r[4], uint32_t saddr) {
    asm volatile("ldmatrix.sync.aligned.m8n8.x4.shared.b16 {%0,%1,%2,%3}, [%4];"
        : "=r"(r[0]), "=r"(r[1]), "=r"(r[2]), "=r"(r[3]) : "r"(saddr));
}

__device__ __forceinline__ void cp16(uint32_t s, const void* g) {
    asm volatile("cp.async.cg.shared.global [%0], [%1], 16;" :: "r"(s), "l"(g));
}
__device__ __forceinline__ void cp_commit() { asm volatile("cp.async.commit_group;"); }
__device__ __forceinline__ void cp_wait0()  { asm volatile("cp.async.wait_group 0;"); }
template<int N>
__device__ __forceinline__ void cp_waitN()  { asm volatile("cp.async.wait_group %0;" :: "n"(N)); }

// =================================================================
// fp32 -> fp16 bulk converter. grid (blocks, 7); 8 floats/thread/iter
// =================================================================
struct CvtArgs {
    const float4* src[7];
    uint4*        dst[7];
    int           n8[7];
};

__global__ __launch_bounds__(256)
void cvt_f16_kernel(CvtArgs a)
{
    const int z = blockIdx.y;
    const float4* __restrict__ s = a.src[z];
    uint4* __restrict__ d = a.dst[z];
    const int n8 = a.n8[z];
    for (int i = blockIdx.x * blockDim.x + threadIdx.x; i < n8;
         i += gridDim.x * blockDim.x) {
        float4 lo = s[2 * i], hi = s[2 * i + 1];
        uint4 u;
        u.x = pack2(lo.x, lo.y); u.y = pack2(lo.z, lo.w);
        u.z = pack2(hi.x, hi.y); u.w = pack2(hi.z, hi.w);
        d[i] = u;
    }
}

// =================================================================
// Shared bits for both GEMM kernels
// =================================================================
struct GemmArgs {
    const __half* A[3];
    const __half* W[3];
    const float*  bias[3];
    void*         out[3];
    float         scale[3];
    int           split[3];
};

#define RPITCH 80    // bytes per smem row: 64B data + 16B pad (conflict-free)

__device__ __forceinline__ void gemm_store(const float acc[4], int m, int n,
                                           const float* bias, float scale,
                                           int split, void* outp)
{
    // acc = {c0,c1,c2,c3} for rows (m, m+8) x cols (n, n+1)
#pragma unroll
    for (int half = 0; half < 2; half++) {
        const int mm = m + half * 8;
        const float v0 = (acc[half * 2 + 0] + bias[n]) * scale;
        const float v1 = (acc[half * 2 + 1] + bias[n + 1]) * scale;
        if (split == 0) {
            float* of = (float*)outp;
            of[(size_t)mm * DMODEL + n] = v0;
            of[(size_t)mm * DMODEL + n + 1] = v1;
        } else {
            const int b = mm >> 11;
            const int sdx = mm & (SEQ - 1);
            const int h = n >> 6;
            const int d = n & (HDIM - 1);
            __half* o16 = (__half*)outp;
            if (split == 1) {
                *(uint32_t*)&o16[(((size_t)(b * NHEAD + h) * SEQ) + sdx) * HDIM + d] =
                    pack2(v0, v1);
            } else {   // transposed [bh][d][s]
                o16[(((size_t)(b * NHEAD + h) * HDIM) + d)     * SEQ + sdx] = __float2half_rn(v0);
                o16[(((size_t)(b * NHEAD + h) * HDIM) + d + 1) * SEQ + sdx] = __float2half_rn(v1);
            }
        }
    }
}

// =================================================================
// GEMM-BIG (QKV): CTA 128x128, 256 thr, warp tile 64x32, NS=4 (round-12 proven)
// =================================================================
#define BSTAGE_B (256 * RPITCH)                 // 20480 B
#define QKV_SMEM (4 * BSTAGE_B)                 // 81920 B

__global__ __launch_bounds__(256, 2)
void gemm_big(GemmArgs args)
{
    extern __shared__ uint32_t gsm[];
    const uint32_t sb = (uint32_t)__cvta_generic_to_shared(gsm);

    const int z = blockIdx.z;
    const __half* __restrict__ A = args.A[z];
    const __half* __restrict__ W = args.W[z];
    const float* __restrict__ bias = args.bias[z];
    const float scale = args.scale[z];
    const int   split = args.split[z];

    const int tid = threadIdx.x;
    const int w = tid >> 5, lane = tid & 31;
    const int gid = lane >> 2, l4 = lane & 3;
    const int bm = blockIdx.x * 128;
    const int bn = blockIdx.y * 128;
    const int wm = (w & 1) * 64;
    const int wn = (w >> 1) * 32;

    const int rowl = lane & 15;
    const int hi16 = (lane >> 4) * 16;

    auto stage = [&](int it, int s) {
        const uint32_t ab = sb + s * BSTAGE_B;
        const uint32_t bb = ab + 128 * RPITCH;
#pragma unroll
        for (int i = 0; i < 4; i++) {           // 256*4/256
            const int idx = i * 256 + tid;
            const int r = idx >> 2;
            const int c = idx & 3;
            if (r < 128)
                cp16(ab + (uint32_t)(r * RPITCH + c * 16),
                     A + (size_t)(bm + r) * DMODEL + it * 32 + c * 8);
            else
                cp16(bb + (uint32_t)((r - 128) * RPITCH + c * 16),
                     W + (size_t)(bn + r - 128) * DMODEL + it * 32 + c * 8);
        }
        cp_commit();
    };

    float acc[4][4][4];
#pragma unroll
    for (int i = 0; i < 4; i++)
#pragma unroll
        for (int j = 0; j < 4; j++)
#pragma unroll
            for (int t = 0; t < 4; t++) acc[i][j][t] = 0.f;

    const int nIter = DMODEL / 32;   // 24
    stage(0, 0); stage(1, 1); stage(2, 2);

    for (int it = 0; it < nIter; it++) {
        const int s = it & 3;
        cp_waitN<2>();
        __syncthreads();

        const uint32_t aB = sb + s * BSTAGE_B;
        const uint32_t bB = aB + 128 * RPITCH;

#pragma unroll
        for (int kb = 0; kb < 64; kb += 32) {
            uint32_t af[4][4], bf[4][2];
#pragma unroll
            for (int mt = 0; mt < 4; mt++)
                ldsm_x4(af[mt], aB + (uint32_t)((wm + mt * 16 + rowl) * RPITCH + kb + hi16));
#pragma unroll
            for (int ntp = 0; ntp < 2; ntp++) {
                uint32_t r[4];
                ldsm_x4(r, bB + (uint32_t)((wn + ntp * 16 + rowl) * RPITCH + kb + hi16));
                bf[2 * ntp][0] = r[0]; bf[2 * ntp][1] = r[2];
                bf[2 * ntp + 1][0] = r[1]; bf[2 * ntp + 1][1] = r[3];
            }
#pragma unroll
            for (int mt = 0; mt < 4; mt++)
#pragma unroll
                for (int nt = 0; nt < 4; nt++)
                    mma_f16(acc[mt][nt], af[mt], bf[nt]);
        }

        if (it + 3 < nIter) stage(it + 3, (it + 3) & 3);
        else                cp_commit();
    }

#pragma unroll
    for (int mt = 0; mt < 4; mt++)
#pragma unroll
        for (int nt = 0; nt < 4; nt++)
            gemm_store(acc[mt][nt], bm + wm + mt * 16 + gid,
                       bn + wn + nt * 8 + 2 * l4, bias, scale, split, args.out[z]);
}

// =================================================================
// GEMM-SMALL (out-proj): CTA 64x128, 256 thr, warp tile 32x32, NS=4 (round-13 proven)
// =================================================================
#define SSTAGE_B (192 * RPITCH)                 // 15360 B
#define OUT_SMEM (4 * SSTAGE_B)                 // 61440 B

__global__ __launch_bounds__(256, 3)
void gemm_small(GemmArgs args)
{
    extern __shared__ uint32_t gsm[];
    const uint32_t sb = (uint32_t)__cvta_generic_to_shared(gsm);

    const int z = blockIdx.z;
    const __half* __restrict__ A = args.A[z];
    const __half* __restrict__ W = args.W[z];
    const float* __restrict__ bias = args.bias[z];
    const float scale = args.scale[z];
    const int   split = args.split[z];

    const int tid = threadIdx.x;
    const int w = tid >> 5, lane = tid & 31;
    const int gid = lane >> 2, l4 = lane & 3;
    const int bm = blockIdx.x * 64;
    const int bn = blockIdx.y * 128;
    const int wm = (w & 1) * 32;
    const int wn = (w >> 1) * 32;

    const int rowl = lane & 15;
    const int hi16 = (lane >> 4) * 16;

    auto stage = [&](int it, int s) {
        const uint32_t ab = sb + s * SSTAGE_B;
        const uint32_t bb = ab + 64 * RPITCH;
#pragma unroll
        for (int i = 0; i < 3; i++) {           // 192*4/256
            const int idx = i * 256 + tid;
            const int r = idx >> 2;
            const int c = idx & 3;
            if (r < 64)
                cp16(ab + (uint32_t)(r * RPITCH + c * 16),
                     A + (size_t)(bm + r) * DMODEL + it * 32 + c * 8);
            else
                cp16(bb + (uint32_t)((r - 64) * RPITCH + c * 16),
                     W + (size_t)(bn + r - 64) * DMODEL + it * 32 + c * 8);
        }
        cp_commit();
    };

    float acc[2][4][4];
#pragma unroll
    for (int i = 0; i < 2; i++)
#pragma unroll
        for (int j = 0; j < 4; j++)
#pragma unroll
            for (int t = 0; t < 4; t++) acc[i][j][t] = 0.f;

    const int nIter = DMODEL / 32;   // 24
    stage(0, 0); stage(1, 1); stage(2, 2);

    for (int it = 0; it < nIter; it++) {
        const int s = it & 3;
        cp_waitN<2>();
        __syncthreads();

        const uint32_t aB = sb + s * SSTAGE_B;
        const uint32_t bB = aB + 64 * RPITCH;

#pragma unroll
        for (int kb = 0; kb < 64; kb += 32) {
            uint32_t af[2][4], bf[4][2];
#pragma unroll
            for (int mt = 0; mt < 2; mt++)
                ldsm_x4(af[mt], aB + (uint32_t)((wm + mt * 16 + rowl) * RPITCH + kb + hi16));
#pragma unroll
            for (int ntp = 0; ntp < 2; ntp++) {
                uint32_t r[4];
                ldsm_x4(r, bB + (uint32_t)((wn + ntp * 16 + rowl) * RPITCH + kb + hi16));
                bf[2 * ntp][0] = r[0]; bf[2 * ntp][1] = r[2];
                bf[2 * ntp + 1][0] = r[1]; bf[2 * ntp + 1][1] = r[3];
            }
#pragma unroll
            for (int mt = 0; mt < 2; mt++)
#pragma unroll
                for (int nt = 0; nt < 4; nt++)
                    mma_f16(acc[mt][nt], af[mt], bf[nt]);
        }

        if (it + 3 < nIter) stage(it + 3, (it + 3) & 3);
        else                cp_commit();
    }

#pragma unroll
    for (int mt = 0; mt < 2; mt++)
#pragma unroll
        for (int nt = 0; nt < 4; nt++)
            gemm_store(acc[mt][nt], bm + wm + mt * 16 + gid,
                       bn + wn + nt * 8 + 2 * l4, bias, scale, split, args.out[z]);
}

// =================================================================
// Flash attention (causal), fp16 mma, shuffle-free PV, exp2 softmax.
// 128 threads (4 warps), q-tile 64. K [bh][s][d], V TRANSPOSED [bh][d][s].
// Q pre-scaled by 0.125*log2(e) so scores are in log2 domain.
// =================================================================
#define KPB 144                               // bytes per smem row (128 data + 16 pad)
#define TB  (64 * KPB)                        // 9216 bytes per tile buffer
#define ATTN_SMEM (4 * TB)                    // 36864 B

__global__ __launch_bounds__(128, 3)
void attn_f16(const __half* __restrict__ Q, const __half* __restrict__ K,
              const __half* __restrict__ V, __half* __restrict__ ctx)
{
    extern __shared__ uint32_t smu[];
    const uint32_t smem_u32 = (uint32_t)__cvta_generic_to_shared(smu);

    const int tid = threadIdx.x;
    const int w = tid >> 5, lane = tid & 31;
    const int gid = lane >> 2, l4 = lane & 3;
    const int bh = blockIdx.x;
    const int qt = (SEQ / 64 - 1) - blockIdx.y;   // reversed: longest first
    const int m0 = w * 16;

    const int rowl = lane & 15;
    const int hi16 = (lane >> 4) * 16;

    const __half* Kg = K + ((size_t)bh * SEQ) * HDIM;   // [s][d]
    const __half* Vg = V + ((size_t)bh * HDIM) * SEQ;   // [d][s]

    auto stage = [&](int jt, int buf) {
        const uint32_t ksb = smem_u32 + (uint32_t)(buf * TB);
        const uint32_t vsb = smem_u32 + (uint32_t)((2 + buf) * TB);
#pragma unroll
        for (int i = 0; i < 8; i++) {
            const int idx = i * 128 + tid;     // 0..1023 cp16 ops
            if (idx < 512) {
                const int r = idx >> 3, c = idx & 7;
                cp16(ksb + (uint32_t)(r * KPB + c * 16),
                     Kg + (size_t)(jt * 64 + r) * HDIM + c * 8);
            } else {
                const int r = (idx - 512) >> 3, c = idx & 7;
                cp16(vsb + (uint32_t)(r * KPB + c * 16),
                     Vg + (size_t)r * SEQ + jt * 64 + c * 8);
            }
        }
        cp_commit();
    };

    // Q fragments directly from gmem (k16 blocks, kt 0..3)
    uint32_t qf[4][4];
    {
        const __half* Qg = Q + ((size_t)bh * SEQ + qt * 64) * HDIM;
#pragma unroll
        for (int kt = 0; kt < 4; kt++) {
            const __half* base = Qg + (m0 + gid) * HDIM + kt * 16 + 2 * l4;
            qf[kt][0] = *(const uint32_t*)(base);
            qf[kt][1] = *(const uint32_t*)(base + 8 * HDIM);
            qf[kt][2] = *(const uint32_t*)(base + 8);
            qf[kt][3] = *(const uint32_t*)(base + 8 * HDIM + 8);
        }
    }

    stage(0, 0);
    cp_wait0();
    __syncthreads();

    float o[8][4];
#pragma unroll
    for (int dt = 0; dt < 8; dt++)
#pragma unroll
        for (int t = 0; t < 4; t++) o[dt][t] = 0.f;

    float m_a = -1e30f, m_b = -1e30f;
    float l_a = 0.f, l_b = 0.f;

    const int ntiles = qt + 1;
    for (int jt = 0; jt < ntiles; jt++) {
        const int buf = jt & 1;
        if (jt + 1 < ntiles) stage(jt + 1, buf ^ 1);

        const uint32_t ksB = smem_u32 + (uint32_t)(buf * TB);
        const uint32_t vtB = smem_u32 + (uint32_t)((2 + buf) * TB);

        // ---- S = Q K^T (log2-domain scores) ----
        float s[8][4];
#pragma unroll
        for (int nt = 0; nt < 8; nt++)
#pragma unroll
            for (int t = 0; t < 4; t++) s[nt][t] = 0.f;

#pragma unroll
        for (int kt = 0; kt < 4; kt++) {
            uint32_t bf[8][2];
#pragma unroll
            for (int ntp = 0; ntp < 4; ntp++) {
                uint32_t r[4];
                ldsm_x4(r, ksB + (uint32_t)((ntp * 16 + rowl) * KPB + kt * 32 + hi16));
                bf[2 * ntp][0] = r[0]; bf[2 * ntp][1] = r[2];
                bf[2 * ntp + 1][0] = r[1]; bf[2 * ntp + 1][1] = r[3];
            }
#pragma unroll
            for (int nt = 0; nt < 8; nt++)
                mma_f16(s[nt], qf[kt], bf[nt]);
        }

        // ---- causal mask on diagonal tile ----
        if (jt == qt) {
            const int ra = m0 + gid, rb = ra + 8;
#pragma unroll
            for (int nt = 0; nt < 8; nt++) {
                const int c = nt * 8 + 2 * l4;
                if (c > ra)     s[nt][0] = -1e30f;
                if (c + 1 > ra) s[nt][1] = -1e30f;
                if (c > rb)     s[nt][2] = -1e30f;
                if (c + 1 > rb) s[nt][3] = -1e30f;
            }
        }

        // ---- online softmax (base-2) ----
        float mxa = -1e30f, mxb = -1e30f;
#pragma unroll
        for (int nt = 0; nt < 8; nt++) {
            mxa = fmaxf(mxa, fmaxf(s[nt][0], s[nt][1]));
            mxb = fmaxf(mxb, fmaxf(s[nt][2], s[nt][3]));
        }
        mxa = fmaxf(mxa, __shfl_xor_sync(0xffffffffu, mxa, 1));
        mxa = fmaxf(mxa, __shfl_xor_sync(0xffffffffu, mxa, 2));
        mxb = fmaxf(mxb, __shfl_xor_sync(0xffffffffu, mxb, 1));
        mxb = fmaxf(mxb, __shfl_xor_sync(0xffffffffu, mxb, 2));

        const float mna = fmaxf(m_a, mxa);
        const float mnb = fmaxf(m_b, mxb);
        const float alpha_a = ex2(m_a - mna);
        const float alpha_b = ex2(m_b - mnb);
        m_a = mna; m_b = mnb;

        float suma = 0.f, sumb = 0.f;
#pragma unroll
        for (int nt = 0; nt < 8; nt++) {
            s[nt][0] = ex2(s[nt][0] - mna);
            s[nt][1] = ex2(s[nt][1] - mna);
            s[nt][2] = ex2(s[nt][2] - mnb);
            s[nt][3] = ex2(s[nt][3] - mnb);
            suma += s[nt][0] + s[nt][1];
            sumb += s[nt][2] + s[nt][3];
        }
        l_a = l_a * alpha_a + suma;
        l_b = l_b * alpha_b + sumb;

#pragma unroll
        for (int dt = 0; dt < 8; dt++) {
            o[dt][0] *= alpha_a; o[dt][1] *= alpha_a;
            o[dt][2] *= alpha_b; o[dt][3] *= alpha_b;
        }

        // ---- O += P V : fp16 P fragment == C fragment layout (no shuffles) ----
#pragma unroll
        for (int kt = 0; kt < 4; kt++) {
            uint32_t pf[4];
            pf[0] = pack2(s[2 * kt][0],     s[2 * kt][1]);
            pf[1] = pack2(s[2 * kt][2],     s[2 * kt][3]);
            pf[2] = pack2(s[2 * kt + 1][0], s[2 * kt + 1][1]);
            pf[3] = pack2(s[2 * kt + 1][2], s[2 * kt + 1][3]);

            uint32_t bv[8][2];
#pragma unroll
            for (int dtp = 0; dtp < 4; dtp++) {
                uint32_t r[4];
                ldsm_x4(r, vtB + (uint32_t)((dtp * 16 + rowl) * KPB + kt * 32 + hi16));
                bv[2 * dtp][0] = r[0]; bv[2 * dtp][1] = r[2];
                bv[2 * dtp + 1][0] = r[1]; bv[2 * dtp + 1][1] = r[3];
            }
#pragma unroll
            for (int dt = 0; dt < 8; dt++)
                mma_f16(o[dt], pf, bv[dt]);
        }

        cp_wait0();
        __syncthreads();
    }

    // ---- finalize ----
    l_a += __shfl_xor_sync(0xffffffffu, l_a, 1);
    l_a += __shfl_xor_sync(0xffffffffu, l_a, 2);
    l_b += __shfl_xor_sync(0xffffffffu, l_b, 1);
    l_b += __shfl_xor_sync(0xffffffffu, l_b, 2);
    const float ia = 1.f / l_a, ib = 1.f / l_b;

    const int b = bh / NHEAD;
    const int h = bh % NHEAD;
    const int sa = qt * 64 + m0 + gid;
    const int sb2 = sa + 8;
    __half* da = ctx + ((size_t)(b * SEQ + sa)) * DMODEL + h * HDIM;
    __half* db = ctx + ((size_t)(b * SEQ + sb2)) * DMODEL + h * HDIM;
#pragma unroll
    for (int dt = 0; dt < 8; dt++) {
        const int c = dt * 8 + 2 * l4;       // even
        *(uint32_t*)&da[c] = pack2(o[dt][0] * ia, o[dt][1] * ia);
        *(uint32_t*)&db[c] = pack2(o[dt][2] * ib, o[dt][3] * ib);
    }
}

// =================================================================
extern "C" void kernel_launch(void* const* d_in, const int* in_sizes, int n_in,
                              void* d_out, int out_size)
{
    (void)in_sizes; (void)n_in; (void)out_size;
    const float* query = (const float*)d_in[0];
    const float* key   = (const float*)d_in[1];
    const float* value = (const float*)d_in[2];
    const float* Wq = (const float*)d_in[4];
    const float* bq = (const float*)d_in[5];
    const float* Wk = (const float*)d_in[6];
    const float* bk = (const float*)d_in[7];
    const float* Wv = (const float*)d_in[8];
    const float* bv = (const float*)d_in[9];
    const float* Wo = (const float*)d_in[10];
    const float* bo = (const float*)d_in[11];
    float* out = (float*)d_out;

    __half *qp, *kp, *vp, *cp;
    __half *aq, *ak, *av, *wq, *wk, *wv, *wo;
    cudaGetSymbolAddress((void**)&qp, g_q);
    cudaGetSymbolAddress((void**)&kp, g_k);
    cudaGetSymbolAddress((void**)&vp, g_v);
    cudaGetSymbolAddress((void**)&cp, g_ctx);
    cudaGetSymbolAddress((void**)&aq, g_aq);
    cudaGetSymbolAddress((void**)&ak, g_ak);
    cudaGetSymbolAddress((void**)&av, g_av);
    cudaGetSymbolAddress((void**)&wq, g_wq);
    cudaGetSymbolAddress((void**)&wk, g_wk);
    cudaGetSymbolAddress((void**)&wv, g_wv);
    cudaGetSymbolAddress((void**)&wo, g_wo);

    static bool init = false;
    if (!init) {
        cudaFuncSetAttribute(attn_f16,   cudaFuncAttributeMaxDynamicSharedMemorySize, ATTN_SMEM);
        cudaFuncSetAttribute(gemm_big,   cudaFuncAttributeMaxDynamicSharedMemorySize, QKV_SMEM);
        cudaFuncSetAttribute(gemm_small, cudaFuncAttributeMaxDynamicSharedMemorySize, OUT_SMEM);
        init = true;
    }

    // ---- pre-convert all operands to fp16 ----
    CvtArgs cv;
    cv.src[0] = (const float4*)query; cv.dst[0] = (uint4*)aq; cv.n8[0] = MROWS * DMODEL / 8;
    cv.src[1] = (const float4*)key;   cv.dst[1] = (uint4*)ak; cv.n8[1] = MROWS * DMODEL / 8;
    cv.src[2] = (const float4*)value; cv.dst[2] = (uint4*)av; cv.n8[2] = MROWS * DMODEL / 8;
    cv.src[3] = (const float4*)Wq;    cv.dst[3] = (uint4*)wq; cv.n8[3] = DMODEL * DMODEL / 8;
    cv.src[4] = (const float4*)Wk;    cv.dst[4] = (uint4*)wk; cv.n8[4] = DMODEL * DMODEL / 8;
    cv.src[5] = (const float4*)Wv;    cv.dst[5] = (uint4*)wv; cv.n8[5] = DMODEL * DMODEL / 8;
    cv.src[6] = (const float4*)Wo;    cv.dst[6] = (uint4*)wo; cv.n8[6] = DMODEL * DMODEL / 8;
    cvt_f16_kernel<<<dim3(256, 7), 256>>>(cv);

    // ---- fused QKV projections (Q scaled by 0.125*log2(e) for exp2 softmax) ----
    GemmArgs qkv;
    qkv.A[0] = aq; qkv.A[1] = ak; qkv.A[2] = av;
    qkv.W[0] = wq; qkv.W[1] = wk; qkv.W[2] = wv;
    qkv.bias[0] = bq; qkv.bias[1] = bk; qkv.bias[2] = bv;
    qkv.out[0] = qp;  qkv.out[1] = kp;  qkv.out[2] = vp;
    qkv.scale[0] = 0.125f * 1.44269504088896f; qkv.scale[1] = 1.f; qkv.scale[2] = 1.f;
    qkv.split[0] = 1; qkv.split[1] = 1; qkv.split[2] = 2;
    dim3 gqkv(MROWS / 128, DMODEL / 128, 3);      // (32, 6, 3)
    gemm_big<<<gqkv, 256, QKV_SMEM>>>(qkv);

    // ---- attention (round-10 proven config, exp2 softmax) ----
    dim3 gattn(BHEADS, SEQ / 64);                 // (24, 32)
    attn_f16<<<gattn, 128, ATTN_SMEM>>>(qp, kp, vp, cp);

    // ---- output projection (64x128 tiles, round-13 proven) ----
    GemmArgs og;
    og.A[0] = cp; og.W[0] = wo; og.bias[0] = bo; og.out[0] = out;
    og.scale[0] = 1.f; og.split[0] = 0;
    og.A[1] = og.A[2] = cp; og.W[1] = og.W[2] = wo;
    og.bias[1] = og.bias[2] = bo; og.out[1] = og.out[2] = out;
    og.scale[1] = og.scale[2] = 1.f; og.split[1] = og.split[2] = 0;
    dim3 gout(MROWS / 64, DMODEL / 128, 1);       // (64, 6)
    gemm_small<<<gout, 256, OUT_SMEM>>>(og);
}